// round 2
// baseline (speedup 1.0000x reference)
#include <cuda_runtime.h>
#include <math.h>

#define T_TOK 8192
#define D_DIM 4096
#define KS 4
#define N_SLOTS 128
#define TOPK 1024
#define MAX_ENTRIES 4096   // TOPK * KS worst case into one slot

// ---------------- scratch (static device globals; no allocation) ----------
__device__ float g_importance[T_TOK];
__device__ int   g_slot_cnt[N_SLOTS];
__device__ int   g_slot_tokens[N_SLOTS * MAX_ENTRIES];

// ---------------------------------------------------------------------------
// Kernel 1: per-token importance.
// importance = ||h|| * (1 + entropy/log(Ks)) + sigmoid(h.W + b)
// One block per token row (16KB), 128 threads, float4 loads.
// ---------------------------------------------------------------------------
__global__ void importance_kernel(const float* __restrict__ h,
                                  const float* __restrict__ attn,
                                  const float* __restrict__ W,
                                  const float* __restrict__ b) {
    int t = blockIdx.x;
    const float4* hr = reinterpret_cast<const float4*>(h + (size_t)t * D_DIM);
    const float4* wr = reinterpret_cast<const float4*>(W);

    float hh = 0.f, hw = 0.f;
#pragma unroll
    for (int j = 0; j < 8; j++) {
        int i = threadIdx.x + j * 128;
        float4 a = hr[i];
        float4 w = wr[i];
        hh += a.x * a.x + a.y * a.y + a.z * a.z + a.w * a.w;
        hw += a.x * w.x + a.y * w.y + a.z * w.z + a.w * w.w;
    }
#pragma unroll
    for (int off = 16; off; off >>= 1) {
        hh += __shfl_xor_sync(0xFFFFFFFFu, hh, off);
        hw += __shfl_xor_sync(0xFFFFFFFFu, hw, off);
    }
    __shared__ float s_hh[4], s_hw[4];
    int wid = threadIdx.x >> 5;
    if ((threadIdx.x & 31) == 0) { s_hh[wid] = hh; s_hw[wid] = hw; }
    __syncthreads();
    if (threadIdx.x == 0) {
        hh = s_hh[0] + s_hh[1] + s_hh[2] + s_hh[3];
        hw = s_hw[0] + s_hw[1] + s_hw[2] + s_hw[3];
        float mag = sqrtf(hh);
        float4 a4 = *reinterpret_cast<const float4*>(attn + t * 4);
        float ent = -(a4.x * logf(a4.x + 1e-8f) + a4.y * logf(a4.y + 1e-8f) +
                      a4.z * logf(a4.z + 1e-8f) + a4.w * logf(a4.w + 1e-8f));
        float surprise = ent * (1.0f / 1.3862943611198906f);   // / log(4)
        float learned = 1.0f / (1.0f + expf(-(hw + b[0])));
        g_importance[t] = mag * (1.0f + surprise) + learned;
    }
}

// ---------------------------------------------------------------------------
// Kernel 2: exact top-1024 selection (radix select over sortable uint32,
// ties broken toward lowest index to match jax.lax.top_k's selected SET),
// then build per-slot token lists. Single block, all state block-local,
// so CUDA-graph replays are clean.
// ---------------------------------------------------------------------------
__global__ void select_kernel(const int* __restrict__ slot_indices) {
    __shared__ unsigned int su[T_TOK];   // 32 KB sortable keys
    __shared__ int hist[256];
    __shared__ int s_bucket, s_k, s_cnt;
    __shared__ int s_slot_cnt[N_SLOTS];

    int tid = threadIdx.x;

    // load + convert to order-preserving unsigned keys
#pragma unroll
    for (int i = 0; i < 8; i++) {
        int t = tid + i * 1024;
        unsigned int u = __float_as_uint(g_importance[t]);
        u ^= (u & 0x80000000u) ? 0xFFFFFFFFu : 0x80000000u;
        su[t] = u;
    }
    __syncthreads();

    // 4-pass 8-bit radix select for the value v of the TOPK-th largest key
    unsigned int prefix = 0, kmask = 0;
    int k = TOPK;
    for (int shift = 24; shift >= 0; shift -= 8) {
        if (tid < 256) hist[tid] = 0;
        __syncthreads();
#pragma unroll
        for (int i = 0; i < 8; i++) {
            int t = tid + i * 1024;
            unsigned int u = su[t];
            if ((u & kmask) == prefix) atomicAdd(&hist[(u >> shift) & 255], 1);
        }
        __syncthreads();
        if (tid == 0) {
            int cum = 0, bsel = 0;
            for (int bb = 255; bb >= 0; bb--) {
                cum += hist[bb];
                if (cum >= k) { bsel = bb; s_k = k - (cum - hist[bb]); break; }
            }
            s_bucket = bsel;
        }
        __syncthreads();
        prefix |= ((unsigned int)s_bucket) << shift;
        kmask  |= 0xFFu << shift;
        k = s_k;
        __syncthreads();
    }
    unsigned int v = prefix;
    int r = k;   // need r elements among keys == v, taken at smallest indices

    // count ties
    if (tid == 0) s_cnt = 0;
    __syncthreads();
    {
        int c = 0;
#pragma unroll
        for (int i = 0; i < 8; i++) { int t = tid + i * 1024; c += (su[t] == v); }
        atomicAdd(&s_cnt, c);
    }
    __syncthreads();
    int m = s_cnt;

    // binary search index threshold X: smallest X with |{t < X : key==v}| >= r
    int X = T_TOK;
    if (r < m) {
        int lo = 0, hi = T_TOK;
        while (lo < hi) {
            int mid = (lo + hi) >> 1;
            __syncthreads();
            if (tid == 0) s_cnt = 0;
            __syncthreads();
            int c = 0;
#pragma unroll
            for (int i = 0; i < 8; i++) {
                int t = tid + i * 1024;
                c += (t < mid && su[t] == v);
            }
            atomicAdd(&s_cnt, c);
            __syncthreads();
            int got = s_cnt;
            __syncthreads();
            if (got >= r) hi = mid; else lo = mid + 1;
        }
        X = lo;
    }

    // build per-slot token lists
    if (tid < N_SLOTS) s_slot_cnt[tid] = 0;
    __syncthreads();
#pragma unroll
    for (int i = 0; i < 8; i++) {
        int t = tid + i * 1024;
        unsigned int u = su[t];
        if (u > v || (u == v && t < X)) {
            int4 s4 = *reinterpret_cast<const int4*>(slot_indices + t * KS);
            int s;
            s = s4.x; g_slot_tokens[s * MAX_ENTRIES + atomicAdd(&s_slot_cnt[s], 1)] = t;
            s = s4.y; g_slot_tokens[s * MAX_ENTRIES + atomicAdd(&s_slot_cnt[s], 1)] = t;
            s = s4.z; g_slot_tokens[s * MAX_ENTRIES + atomicAdd(&s_slot_cnt[s], 1)] = t;
            s = s4.w; g_slot_tokens[s * MAX_ENTRIES + atomicAdd(&s_slot_cnt[s], 1)] = t;
        }
    }
    __syncthreads();
    if (tid < N_SLOTS) g_slot_cnt[tid] = s_slot_cnt[tid];
}

// ---------------------------------------------------------------------------
// Kernel 3: per-slot gather-sum, mean, EMA write. One block per
// (slot, 512-column chunk). 4-way unrolled over the token list for MLP.
// ---------------------------------------------------------------------------
__global__ void aggregate_kernel(const float* __restrict__ h,
                                 const float* __restrict__ mem,
                                 float* __restrict__ out) {
    int slot = blockIdx.y;
    int col4 = blockIdx.x * 128 + threadIdx.x;   // float4 index (0..1023)
    int cnt = g_slot_cnt[slot];

    const float4* cur_row = reinterpret_cast<const float4*>(mem + (size_t)slot * D_DIM);
    float4 cur = cur_row[col4];
    float4 res = cur;

    if (cnt > 0) {
        const int* toks = &g_slot_tokens[slot * MAX_ENTRIES];
        float4 a0 = {0, 0, 0, 0}, a1 = {0, 0, 0, 0}, a2 = {0, 0, 0, 0}, a3 = {0, 0, 0, 0};
        int i = 0;
        for (; i + 3 < cnt; i += 4) {
            int t0 = toks[i], t1 = toks[i + 1], t2 = toks[i + 2], t3 = toks[i + 3];
            float4 v0 = reinterpret_cast<const float4*>(h + (size_t)t0 * D_DIM)[col4];
            float4 v1 = reinterpret_cast<const float4*>(h + (size_t)t1 * D_DIM)[col4];
            float4 v2 = reinterpret_cast<const float4*>(h + (size_t)t2 * D_DIM)[col4];
            float4 v3 = reinterpret_cast<const float4*>(h + (size_t)t3 * D_DIM)[col4];
            a0.x += v0.x; a0.y += v0.y; a0.z += v0.z; a0.w += v0.w;
            a1.x += v1.x; a1.y += v1.y; a1.z += v1.z; a1.w += v1.w;
            a2.x += v2.x; a2.y += v2.y; a2.z += v2.z; a2.w += v2.w;
            a3.x += v3.x; a3.y += v3.y; a3.z += v3.z; a3.w += v3.w;
        }
        for (; i < cnt; i++) {
            int t0 = toks[i];
            float4 v0 = reinterpret_cast<const float4*>(h + (size_t)t0 * D_DIM)[col4];
            a0.x += v0.x; a0.y += v0.y; a0.z += v0.z; a0.w += v0.w;
        }
        float inv = 1.0f / (float)cnt;
        float sx = (a0.x + a1.x) + (a2.x + a3.x);
        float sy = (a0.y + a1.y) + (a2.y + a3.y);
        float sz = (a0.z + a1.z) + (a2.z + a3.z);
        float sw = (a0.w + a1.w) + (a2.w + a3.w);
        res.x = 0.1f * (sx * inv) + 0.9f * cur.x;
        res.y = 0.1f * (sy * inv) + 0.9f * cur.y;
        res.z = 0.1f * (sz * inv) + 0.9f * cur.z;
        res.w = 0.1f * (sw * inv) + 0.9f * cur.w;
    }
    reinterpret_cast<float4*>(out)[slot * (D_DIM / 4) + col4] = res;
}

// ---------------------------------------------------------------------------
extern "C" void kernel_launch(void* const* d_in, const int* in_sizes, int n_in,
                              void* d_out, int out_size) {
    const float* hidden = (const float*)d_in[0];   // [8192, 4096]
    const float* attn   = (const float*)d_in[1];   // [8192, 4]
    const float* memory = (const float*)d_in[2];   // [1, 128, 4096]
    const float* W      = (const float*)d_in[3];   // [1, 4096]
    const float* b      = (const float*)d_in[4];   // [1]
    const int*   slots  = (const int*)d_in[5];     // [8192, 4]
    float* out = (float*)d_out;                    // [1, 128, 4096]

    importance_kernel<<<T_TOK, 128>>>(hidden, attn, W, b);
    select_kernel<<<1, 1024>>>(slots);
    aggregate_kernel<<<dim3(8, N_SLOTS), 128>>>(hidden, memory, out);
}